// round 1
// baseline (speedup 1.0000x reference)
#include <cuda_runtime.h>
#include <math.h>

// Problem constants
#define NB   4
#define C3   256
#define HW3  3136
#define C4   512
#define HW4  784
#define EPSV 1e-5f

// ---------------- scratch (static device globals; no allocation) ----------------
__device__ float d_gN3[NB * C3 * HW3];
__device__ float d_tN3[NB * C3 * HW3];
__device__ float d_gN4[NB * C4 * HW4];
__device__ float d_tN4[NB * C4 * HW4];
__device__ float d_cd3[(size_t)NB * HW3 * HW3];   // 157 MB
__device__ float d_cd4[(size_t)NB * HW4 * HW4];   // 9.8 MB
__device__ float d_c03[NB * HW3];
__device__ float d_b3 [NB * HW3];
__device__ float d_c04[NB * HW4];
__device__ float d_b4 [NB * HW4];
__device__ float d_rm3[NB * HW3];
__device__ float d_rm4[NB * HW4];

// ---------------- 1) normalize: center by mean(tar over C), L2-normalize over C --
// block = 128 threads = 4 C-partitions x 32 hw positions; grid = (ceil(HW/32), N)
__global__ __launch_bounds__(128) void normalize_kernel(
    const float* __restrict__ gen, const float* __restrict__ tar,
    float* __restrict__ gN, float* __restrict__ tN, int C, int HW)
{
    int n    = blockIdx.y;
    int lane = threadIdx.x & 31;
    int cp   = threadIdx.x >> 5;          // 0..3
    int hw   = blockIdx.x * 32 + lane;
    bool ok  = hw < HW;

    __shared__ float r1[4][32];
    __shared__ float r2[4][32];

    const float* gp = gen + (size_t)n * C * HW + hw;
    const float* tp = tar + (size_t)n * C * HW + hw;

    float s = 0.f;
    if (ok) {
        #pragma unroll 4
        for (int c = cp; c < C; c += 4) s += tp[(size_t)c * HW];
    }
    r1[cp][lane] = s;
    __syncthreads();
    float mean = (r1[0][lane] + r1[1][lane] + r1[2][lane] + r1[3][lane]) / (float)C;
    __syncthreads();

    float sg = 0.f, st = 0.f;
    if (ok) {
        #pragma unroll 4
        for (int c = cp; c < C; c += 4) {
            float g = gp[(size_t)c * HW] - mean;
            float t = tp[(size_t)c * HW] - mean;
            sg += g * g;
            st += t * t;
        }
    }
    r1[cp][lane] = sg;
    r2[cp][lane] = st;
    __syncthreads();
    float rg = 1.0f / sqrtf(r1[0][lane] + r1[1][lane] + r1[2][lane] + r1[3][lane]);
    float rt = 1.0f / sqrtf(r2[0][lane] + r2[1][lane] + r2[2][lane] + r2[3][lane]);

    if (ok) {
        float* go = gN + (size_t)n * C * HW + hw;
        float* to = tN + (size_t)n * C * HW + hw;
        #pragma unroll 4
        for (int c = cp; c < C; c += 4) {
            go[(size_t)c * HW] = (gp[(size_t)c * HW] - mean) * rg;
            to[(size_t)c * HW] = (tp[(size_t)c * HW] - mean) * rt;
        }
    }
}

// ---------------- 2) GEMM: cd[n][p][q] = (1 - sum_c tN[c][p]*gN[c][q]) / 2 -------
// A = tN viewed as (C x P), B = gN viewed as (C x Q).  128x128x8 tile, 8x8 microtile.
#define BM 128
#define BN 128
#define BKT 8

__global__ __launch_bounds__(256) void gemm_cd_kernel(
    const float* __restrict__ A, const float* __restrict__ B,
    float* __restrict__ CD, int C, int P, int Q)
{
    __shared__ float As[BKT][BM];
    __shared__ float Bs[BKT][BN];

    int n = blockIdx.z;
    const float* An = A + (size_t)n * C * P;
    const float* Bn = B + (size_t)n * C * Q;
    float*       Cn = CD + (size_t)n * P * Q;

    int tid = threadIdx.x;
    int tx = tid & 15, ty = tid >> 4;
    int row0 = blockIdx.y * BM;
    int col0 = blockIdx.x * BN;

    float acc[8][8];
    #pragma unroll
    for (int i = 0; i < 8; i++)
        #pragma unroll
        for (int j = 0; j < 8; j++) acc[i][j] = 0.f;

    for (int k0 = 0; k0 < C; k0 += BKT) {
        #pragma unroll
        for (int i = 0; i < 4; i++) {
            int e  = tid + i * 256;
            int kk = e >> 7;
            int mm = e & 127;
            int ar = row0 + mm;
            int bc = col0 + mm;
            As[kk][mm] = (ar < P) ? An[(size_t)(k0 + kk) * P + ar] : 0.f;
            Bs[kk][mm] = (bc < Q) ? Bn[(size_t)(k0 + kk) * Q + bc] : 0.f;
        }
        __syncthreads();

        #pragma unroll
        for (int kk = 0; kk < BKT; kk++) {
            float4 a0 = *(const float4*)&As[kk][ty * 8];
            float4 a1 = *(const float4*)&As[kk][ty * 8 + 4];
            float4 b0 = *(const float4*)&Bs[kk][tx * 8];
            float4 b1 = *(const float4*)&Bs[kk][tx * 8 + 4];
            float a[8] = {a0.x, a0.y, a0.z, a0.w, a1.x, a1.y, a1.z, a1.w};
            float b[8] = {b0.x, b0.y, b0.z, b0.w, b1.x, b1.y, b1.z, b1.w};
            #pragma unroll
            for (int i = 0; i < 8; i++)
                #pragma unroll
                for (int j = 0; j < 8; j++)
                    acc[i][j] = fmaf(a[i], b[j], acc[i][j]);
        }
        __syncthreads();
    }

    #pragma unroll
    for (int i = 0; i < 8; i++) {
        int r = row0 + ty * 8 + i;
        if (r < P) {
            #pragma unroll
            for (int j = 0; j < 8; j++) {
                int c = col0 + tx * 8 + j;
                if (c < Q)
                    Cn[(size_t)r * Q + c] = 0.5f * (1.0f - acc[i][j]);
            }
        }
    }
}

// ---------------- 3) column min over p -> c0_q = -2/(min + eps) ------------------
// block = 256 = 32 cols x 8 row-slices; grid = (ceil(Q/32), N)
__global__ __launch_bounds__(256) void colmin_kernel(
    const float* __restrict__ CD, float* __restrict__ c0, int P, int Q)
{
    int n    = blockIdx.y;
    int lane = threadIdx.x & 31;
    int rs   = threadIdx.x >> 5;
    int q    = blockIdx.x * 32 + lane;
    const float* Cn = CD + (size_t)n * P * Q;

    float m = __int_as_float(0x7f800000);  // +inf
    if (q < Q) {
        #pragma unroll 4
        for (int p = rs; p < P; p += 8)
            m = fminf(m, Cn[(size_t)p * Q + q]);
    }
    __shared__ float red[256];
    red[threadIdx.x] = m;
    __syncthreads();
    if (threadIdx.x < 128) red[threadIdx.x] = fminf(red[threadIdx.x], red[threadIdx.x + 128]);
    __syncthreads();
    if (threadIdx.x < 64)  red[threadIdx.x] = fminf(red[threadIdx.x], red[threadIdx.x + 64]);
    __syncthreads();
    if (threadIdx.x < 32) {
        float v = fminf(red[threadIdx.x], red[threadIdx.x + 32]);
        if (q < Q) c0[n * Q + q] = -2.0f / (v + EPSV);
    }
}

// ---------------- 4) column sum of e = exp(2 + c0*cd) -> b_q = 2 - log(S_q) ------
__global__ __launch_bounds__(256) void colsum_kernel(
    const float* __restrict__ CD, const float* __restrict__ c0,
    float* __restrict__ b, int P, int Q)
{
    int n    = blockIdx.y;
    int lane = threadIdx.x & 31;
    int rs   = threadIdx.x >> 5;
    int q    = blockIdx.x * 32 + lane;
    const float* Cn = CD + (size_t)n * P * Q;

    float s = 0.f;
    if (q < Q) {
        float c0q = c0[n * Q + q];
        #pragma unroll 4
        for (int p = rs; p < P; p += 8)
            s += __expf(fmaf(c0q, Cn[(size_t)p * Q + q], 2.0f));
    }
    __shared__ float red[256];
    red[threadIdx.x] = s;
    __syncthreads();
    if (threadIdx.x < 128) red[threadIdx.x] += red[threadIdx.x + 128];
    __syncthreads();
    if (threadIdx.x < 64)  red[threadIdx.x] += red[threadIdx.x + 64];
    __syncthreads();
    if (threadIdx.x < 32) {
        float S = red[threadIdx.x] + red[threadIdx.x + 32];
        if (q < Q) b[n * Q + q] = 2.0f - logf(S);
    }
}

// ---------------- 5) row max (log domain): rm_p = max_q (c0_q*cd + b_q) ----------
// block = 256 = 8 warps, 1 row per warp; grid = (ceil(P/8), N)
__global__ __launch_bounds__(256) void rowmax_kernel(
    const float* __restrict__ CD, const float* __restrict__ c0,
    const float* __restrict__ b, float* __restrict__ rm, int P, int Q)
{
    __shared__ float sc0[HW3];
    __shared__ float sb [HW3];

    int n    = blockIdx.y;
    int warp = threadIdx.x >> 5;
    int lane = threadIdx.x & 31;

    for (int i = threadIdx.x; i < Q; i += 256) {
        sc0[i] = c0[n * Q + i];
        sb[i]  = b [n * Q + i];
    }
    __syncthreads();

    int p = blockIdx.x * 8 + warp;
    if (p < P) {
        const float* row = CD + (size_t)n * P * Q + (size_t)p * Q;
        float m = -__int_as_float(0x7f800000);
        #pragma unroll 4
        for (int q = lane; q < Q; q += 32)
            m = fmaxf(m, fmaf(sc0[q], row[q], sb[q]));
        #pragma unroll
        for (int o = 16; o > 0; o >>= 1)
            m = fmaxf(m, __shfl_xor_sync(0xffffffffu, m, o));
        if (lane == 0) rm[n * P + p] = m;
    }
}

// ---------------- 6) final: sum_n -log(mean_p exp(rm)); combine layers -----------
__global__ __launch_bounds__(256) void final_kernel(
    const float* __restrict__ rm3, const float* __restrict__ rm4,
    float* __restrict__ out)
{
    __shared__ float red[256];
    int tid = threadIdx.x;
    float total = 0.f;

    for (int n = 0; n < NB; n++) {
        float s = 0.f;
        for (int p = tid; p < HW3; p += 256) s += expf(rm3[n * HW3 + p]);
        red[tid] = s;
        __syncthreads();
        for (int o = 128; o > 0; o >>= 1) {
            if (tid < o) red[tid] += red[tid + o];
            __syncthreads();
        }
        total += 0.5f * (-logf(red[0] / (float)HW3));
        __syncthreads();
    }
    for (int n = 0; n < NB; n++) {
        float s = 0.f;
        for (int p = tid; p < HW4; p += 256) s += expf(rm4[n * HW4 + p]);
        red[tid] = s;
        __syncthreads();
        for (int o = 128; o > 0; o >>= 1) {
            if (tid < o) red[tid] += red[tid + o];
            __syncthreads();
        }
        total += 1.0f * (-logf(red[0] / (float)HW4));
        __syncthreads();
    }
    if (tid == 0) out[0] = total;
}

// ---------------- launch ---------------------------------------------------------
extern "C" void kernel_launch(void* const* d_in, const int* in_sizes, int n_in,
                              void* d_out, int out_size)
{
    const float* gen3 = (const float*)d_in[0];
    const float* tar3 = (const float*)d_in[1];
    const float* gen4 = (const float*)d_in[2];
    const float* tar4 = (const float*)d_in[3];

    float *gN3, *tN3, *gN4, *tN4, *cd3, *cd4, *c03, *b3, *c04, *b4, *rm3, *rm4;
    cudaGetSymbolAddress((void**)&gN3, d_gN3);
    cudaGetSymbolAddress((void**)&tN3, d_tN3);
    cudaGetSymbolAddress((void**)&gN4, d_gN4);
    cudaGetSymbolAddress((void**)&tN4, d_tN4);
    cudaGetSymbolAddress((void**)&cd3, d_cd3);
    cudaGetSymbolAddress((void**)&cd4, d_cd4);
    cudaGetSymbolAddress((void**)&c03, d_c03);
    cudaGetSymbolAddress((void**)&b3,  d_b3);
    cudaGetSymbolAddress((void**)&c04, d_c04);
    cudaGetSymbolAddress((void**)&b4,  d_b4);
    cudaGetSymbolAddress((void**)&rm3, d_rm3);
    cudaGetSymbolAddress((void**)&rm4, d_rm4);

    // ---- layer 3 ----
    {
        dim3 gn((HW3 + 31) / 32, NB);
        normalize_kernel<<<gn, 128>>>(gen3, tar3, gN3, tN3, C3, HW3);
        dim3 gg((HW3 + BN - 1) / BN, (HW3 + BM - 1) / BM, NB);
        gemm_cd_kernel<<<gg, 256>>>(tN3, gN3, cd3, C3, HW3, HW3);
        dim3 gc((HW3 + 31) / 32, NB);
        colmin_kernel<<<gc, 256>>>(cd3, c03, HW3, HW3);
        colsum_kernel<<<gc, 256>>>(cd3, c03, b3, HW3, HW3);
        dim3 gr((HW3 + 7) / 8, NB);
        rowmax_kernel<<<gr, 256>>>(cd3, c03, b3, rm3, HW3, HW3);
    }
    // ---- layer 4 ----
    {
        dim3 gn((HW4 + 31) / 32, NB);
        normalize_kernel<<<gn, 128>>>(gen4, tar4, gN4, tN4, C4, HW4);
        dim3 gg((HW4 + BN - 1) / BN, (HW4 + BM - 1) / BM, NB);
        gemm_cd_kernel<<<gg, 256>>>(tN4, gN4, cd4, C4, HW4, HW4);
        dim3 gc((HW4 + 31) / 32, NB);
        colmin_kernel<<<gc, 256>>>(cd4, c04, HW4, HW4);
        colsum_kernel<<<gc, 256>>>(cd4, c04, b4, HW4, HW4);
        dim3 gr((HW4 + 7) / 8, NB);
        rowmax_kernel<<<gr, 256>>>(cd4, c04, b4, rm4, HW4, HW4);
    }

    final_kernel<<<1, 256>>>(rm3, rm4, (float*)d_out);
}